// round 12
// baseline (speedup 1.0000x reference)
#include <cuda_runtime.h>
#include <cuda_fp16.h>
#include <cstdint>
#include <cstddef>

// Problem constants (fixed by the dataset)
#define NROWS 500000
#define HDIM  128
#define PCH   64
#define LSTEPS 50

// ---------------------------------------------------------------------------
// Device scratch (static __device__ arrays only — no allocation allowed)
// ---------------------------------------------------------------------------
__device__ __align__(16) uint2 g_W2[64 * 256];   // action_W  fp16, packed [kgroup][j], 4 k's per uint2
__device__ __align__(16) uint2 g_TW2[64 * 128];  // action_TW fp16, packed [kgroup][j]
__device__ __align__(16) float g_v[256];         // attention @ last_h
__device__ __align__(16) float g_pcache[PCH * HDIM];
__device__ __align__(16) float g_sacc[128 * 257];   // per-stream-block: 256 acc + wsum
__device__ __align__(16) float g_attn[256];
__device__ __align__(16) float g_rg[HDIM];
__device__ __align__(16) float g_zg[HDIM];
__device__ __align__(16) float g_regpart[PCH * HDIM];

// RNN shared-memory layout (dynamic smem): ~198 KB, forces 1 block/SM
struct __align__(16) MainSmem {
    uint2 W2[64 * 256];     // 128 KB
    uint2 TW2[64 * 128];    //  64 KB
    float bA[256];
    float bT[128];
    float xh[256];          // [x (128) | h (128)]
    float rh[128];          // r * h
    float zb[128];          // z gate
    float hcur[128];
    float red[512];         // split-k partials
    int   acts[64];         // staged action ids for this chain
};

// Dtype-agnostic integer-index read: is64 selects int64 vs int32 layout.
__device__ __forceinline__ int ag579_read_idx(const void* buf, int i, int is64) {
    if (is64) return (int)((const long long*)buf)[i];
    return ((const int*)buf)[i];
}

// ---------------------------------------------------------------------------
// K0: v = attention @ last_h  (block 0), weight transpose+fp16 (blocks 1..64)
// ---------------------------------------------------------------------------
__global__ void ag579_k0_setup(const float* __restrict__ att, const float* __restrict__ lh,
                               const float* __restrict__ W, const float* __restrict__ TW)
{
    int b = blockIdx.x, tid = threadIdx.x;
    if (b == 0) {
        __shared__ float s_lh[128];
        if (tid < 128) s_lh[tid] = lh[tid];
        __syncthreads();
        int w = tid >> 5, l = tid & 31;
        float4 lv = *(const float4*)&s_lh[l * 4];
        #pragma unroll 4
        for (int t = 0; t < 32; t++) {
            int i = w + 8 * t;   // 256 rows over 8 warps
            float4 a = *(const float4*)(att + (size_t)i * 128 + l * 4);
            float p = a.x * lv.x + a.y * lv.y + a.z * lv.z + a.w * lv.w;
            #pragma unroll
            for (int o = 16; o; o >>= 1) p += __shfl_xor_sync(0xffffffffu, p, o);
            if (l == 0) g_v[i] = p;
        }
    } else {
        int kg = b - 1;   // 0..63  -> k = 4*kg .. 4*kg+3
        {
            // action_W: (256 out, 256 in). g_W2[kg*256 + j] = half4 of W[j][4kg..4kg+3]
            float4 wv = *(const float4*)(W + (size_t)tid * 256 + kg * 4);
            __half2 ha = __floats2half2_rn(wv.x, wv.y);
            __half2 hb = __floats2half2_rn(wv.z, wv.w);
            uint2 o;
            o.x = *reinterpret_cast<unsigned int*>(&ha);
            o.y = *reinterpret_cast<unsigned int*>(&hb);
            g_W2[kg * 256 + tid] = o;
        }
        if (tid < 128) {
            float4 wv = *(const float4*)(TW + (size_t)tid * 256 + kg * 4);
            __half2 ha = __floats2half2_rn(wv.x, wv.y);
            __half2 hb = __floats2half2_rn(wv.z, wv.w);
            uint2 o;
            o.x = *reinterpret_cast<unsigned int*>(&ha);
            o.y = *reinterpret_cast<unsigned int*>(&hb);
            g_TW2[kg * 128 + tid] = o;
        }
    }
}

// ---------------------------------------------------------------------------
// Main kernel: blocks [0,64) = RNN chains; blocks [64, 64+NSB) = streaming
// actions/parent passed as void* — dtype (int32 vs int64) detected on device.
// ---------------------------------------------------------------------------
__global__ void __launch_bounds__(512, 1)
ag579_main_kernel(const float* __restrict__ down, const float* __restrict__ up,
                  const float* __restrict__ act_embed,
                  const float* __restrict__ action_b, const float* __restrict__ action_Tb,
                  const void* __restrict__ actions_raw, const void* __restrict__ parent_raw,
                  int NSB)
{
    extern __shared__ __align__(16) char smem_raw[];
    int tid = threadIdx.x;

    if (blockIdx.x < 64) {
        // ===================== RNN chain block =====================
        MainSmem* sm = (MainSmem*)smem_raw;
        __shared__ int s_is64;
        int p = blockIdx.x;

        // Detect index dtype: int64-LE with small values => odd 32-bit words are 0.
        // Under int32 (values in [0,128)), all-16-zero has probability 128^-16.
        if (tid == 0) {
            const int* a32 = (const int*)actions_raw;
            int z = 1;
            #pragma unroll
            for (int i = 0; i < 16; i++) z &= (a32[2 * i + 1] == 0);
            s_is64 = z;
        }

        // Load fp16 weights into smem (192 KB; L2-resident after wave start)
        {
            const uint4* src = (const uint4*)g_W2;
            uint4* dst = (uint4*)sm->W2;
            for (int i = tid; i < 8192; i += 512) dst[i] = src[i];
            const uint4* src2 = (const uint4*)g_TW2;
            uint4* dst2 = (uint4*)sm->TW2;
            for (int i = tid; i < 4096; i += 512) dst2[i] = src2[i];
        }
        __syncthreads();   // s_is64 visible; weight copy done

        int is64 = s_is64;
        if (tid < 256) sm->bA[tid] = action_b[tid];
        else if (tid < 384) sm->bT[tid - 256] = action_Tb[tid - 256];
        else if (tid >= 448 && tid < 448 + LSTEPS)   // stage all action ids once
            sm->acts[tid - 448] = ag579_read_idx(actions_raw, p * LSTEPS + (tid - 448), is64);
        if (tid < 128) {
            int par = ag579_read_idx(parent_raw, p, is64);
            float h0 = down[(size_t)par * 128 + tid];
            sm->hcur[tid] = h0;
            sm->xh[128 + tid] = h0;
            int a0 = ag579_read_idx(actions_raw, p * LSTEPS, is64);
            sm->xh[tid] = act_embed[(size_t)a0 * 128 + tid];
        }
        __syncthreads();

        int j    = tid & 255, half = tid >> 8;   // phase A: 2-way split-k
        int jb   = tid & 127, q    = tid >> 7;   // phase B: 4-way split-k
        const float* xsrcB = (q < 2) ? sm->xh : sm->rh;
        int goffB = (q < 2) ? 0 : 128;

        for (int l = 0; l < LSTEPS; l++) {
            // prefetch next step's embedding row (latency hidden under phases A+B)
            float xnext = 0.f;
            if (tid < 128 && l < LSTEPS - 1) {
                int an = sm->acts[l + 1];
                xnext = __ldg(&act_embed[(size_t)an * 128 + tid]);
            }

            // ---- phase A: a = sigmoid([x,h] @ W.T + b) ----
            float sum = 0.f;
            #pragma unroll
            for (int i = 0; i < 32; i++) {
                int kg = half * 32 + i;
                uint2 w = sm->W2[kg * 256 + j];
                float4 xv = *(const float4*)&sm->xh[kg * 4];
                __half2 h01 = *reinterpret_cast<__half2*>(&w.x);
                __half2 h23 = *reinterpret_cast<__half2*>(&w.y);
                float2 f01 = __half22float2(h01);
                float2 f23 = __half22float2(h23);
                sum = fmaf(f01.x, xv.x, sum);
                sum = fmaf(f01.y, xv.y, sum);
                sum = fmaf(f23.x, xv.z, sum);
                sum = fmaf(f23.y, xv.w, sum);
            }
            sm->red[tid] = sum;
            __syncthreads();
            if (tid < 256) {
                float s = sm->red[tid] + sm->red[tid + 256] + sm->bA[tid];
                float a = 1.f / (1.f + __expf(-s));
                if (tid < 128) sm->rh[tid] = a * sm->hcur[tid];   // r * h
                else           sm->zb[tid - 128] = a;             // z
            }
            __syncthreads();

            // ---- phase B: t = tanh([x, r*h] @ TW.T + Tb) ----
            sum = 0.f;
            #pragma unroll
            for (int i = 0; i < 16; i++) {
                int kg = q * 16 + i;
                uint2 w = sm->TW2[kg * 128 + jb];
                float4 xv = *(const float4*)&xsrcB[kg * 4 - goffB];
                __half2 h01 = *reinterpret_cast<__half2*>(&w.x);
                __half2 h23 = *reinterpret_cast<__half2*>(&w.y);
                float2 f01 = __half22float2(h01);
                float2 f23 = __half22float2(h23);
                sum = fmaf(f01.x, xv.x, sum);
                sum = fmaf(f01.y, xv.y, sum);
                sum = fmaf(f23.x, xv.z, sum);
                sum = fmaf(f23.y, xv.w, sum);
            }
            sm->red[tid] = sum;
            __syncthreads();
            if (tid < 128) {
                float s = sm->red[tid] + sm->red[tid + 128] +
                          sm->red[tid + 256] + sm->red[tid + 384] + sm->bT[tid];
                float t = tanhf(s);
                float z = sm->zb[tid];
                float h = sm->hcur[tid];
                float hn = (1.f - z) * h + z * t;
                sm->hcur[tid] = hn;
                sm->xh[128 + tid] = hn;
                if (l < LSTEPS - 1) sm->xh[tid] = xnext;   // commit prefetched x
            }
            __syncthreads();
        }
        if (tid < 128) g_pcache[p * 128 + tid] = sm->hcur[tid];

    } else {
        // ===================== streaming block =====================
        int sb = blockIdx.x - 64;
        float* sred = (float*)smem_raw;    // [16][257]
        int w = tid >> 5, l = tid & 31;

        float4 vd = *(const float4*)&g_v[l * 4];
        float4 vu = *(const float4*)&g_v[128 + l * 4];

        int chunk = (NROWS + NSB - 1) / NSB;
        int r0 = sb * chunk;
        int r1 = min(NROWS, r0 + chunk);

        float4 ad = make_float4(0.f, 0.f, 0.f, 0.f);
        float4 au = make_float4(0.f, 0.f, 0.f, 0.f);
        float wsum = 0.f;

        int r = r0 + w;
        // unroll-6: 12 LDG.128 in flight per warp (~24 KB/SM) to cover DRAM latency
        for (; r + 80 < r1; r += 96) {
            float4 d[6], u[6];
            #pragma unroll
            for (int t = 0; t < 6; t++) {
                const float* rowd = down + (size_t)(r + 16 * t) * 128;
                const float* rowu = up   + (size_t)(r + 16 * t) * 128;
                d[t] = __ldcs((const float4*)(rowd + l * 4));
                u[t] = __ldcs((const float4*)(rowu + l * 4));
            }
            #pragma unroll
            for (int t = 0; t < 6; t++) {
                float pr = d[t].x * vd.x + d[t].y * vd.y + d[t].z * vd.z + d[t].w * vd.w
                         + u[t].x * vu.x + u[t].y * vu.y + u[t].z * vu.z + u[t].w * vu.w;
                #pragma unroll
                for (int o = 16; o; o >>= 1) pr += __shfl_xor_sync(0xffffffffu, pr, o);
                wsum += pr;
                ad.x = fmaf(pr, d[t].x, ad.x); ad.y = fmaf(pr, d[t].y, ad.y);
                ad.z = fmaf(pr, d[t].z, ad.z); ad.w = fmaf(pr, d[t].w, ad.w);
                au.x = fmaf(pr, u[t].x, au.x); au.y = fmaf(pr, u[t].y, au.y);
                au.z = fmaf(pr, u[t].z, au.z); au.w = fmaf(pr, u[t].w, au.w);
            }
        }
        for (; r < r1; r += 16) {
            const float* rowd = down + (size_t)r * 128;
            const float* rowu = up   + (size_t)r * 128;
            float4 d = __ldcs((const float4*)(rowd + l * 4));
            float4 u = __ldcs((const float4*)(rowu + l * 4));
            float pr = d.x * vd.x + d.y * vd.y + d.z * vd.z + d.w * vd.w
                     + u.x * vu.x + u.y * vu.y + u.z * vu.z + u.w * vu.w;
            #pragma unroll
            for (int o = 16; o; o >>= 1) pr += __shfl_xor_sync(0xffffffffu, pr, o);
            wsum += pr;
            ad.x = fmaf(pr, d.x, ad.x); ad.y = fmaf(pr, d.y, ad.y);
            ad.z = fmaf(pr, d.z, ad.z); ad.w = fmaf(pr, d.w, ad.w);
            au.x = fmaf(pr, u.x, au.x); au.y = fmaf(pr, u.y, au.y);
            au.z = fmaf(pr, u.z, au.z); au.w = fmaf(pr, u.w, au.w);
        }

        // cross-warp reduction in smem
        sred[w * 257 + l * 4 + 0] = ad.x;
        sred[w * 257 + l * 4 + 1] = ad.y;
        sred[w * 257 + l * 4 + 2] = ad.z;
        sred[w * 257 + l * 4 + 3] = ad.w;
        sred[w * 257 + 128 + l * 4 + 0] = au.x;
        sred[w * 257 + 128 + l * 4 + 1] = au.y;
        sred[w * 257 + 128 + l * 4 + 2] = au.z;
        sred[w * 257 + 128 + l * 4 + 3] = au.w;
        if (l == 0) sred[w * 257 + 256] = wsum;
        __syncthreads();
        if (tid < 256) {
            float s = 0.f;
            #pragma unroll
            for (int ww = 0; ww < 16; ww++) s += sred[ww * 257 + tid];
            g_sacc[sb * 257 + tid] = s;
        } else if (tid == 256) {
            float s = 0.f;
            #pragma unroll
            for (int ww = 0; ww < 16; ww++) s += sred[ww * 257 + 256];
            g_sacc[sb * 257 + 256] = s;
        }
    }
}

// ---------------------------------------------------------------------------
// K2: combine stream partials -> attention_state; hm; r/z gates
// ---------------------------------------------------------------------------
__global__ void ag579_k2_combine(const float* __restrict__ down, const float* __restrict__ up,
                                 const float* __restrict__ schedW, const float* __restrict__ schedWb,
                                 const float* __restrict__ schedU, const float* __restrict__ schedUb,
                                 const int* __restrict__ op_idx_p, int NSB)
{
    __shared__ float sx[384];
    __shared__ float swsum;
    int tid = threadIdx.x;   // 256
    int op = op_idx_p[0];    // value 0; low word is 0 under int32 or int64-LE

    if (tid == 0) {
        float s = 0.f;
        for (int b = 0; b < NSB; b++) s += g_sacc[b * 257 + 256];
        swsum = s;
    }
    if (tid < 128) {
        float s = 0.f;
        #pragma unroll 8
        for (int p = 0; p < PCH; p++) s += g_pcache[p * 128 + tid];
        sx[256 + tid] = s * (1.f / (float)PCH);      // hm
        sx[tid]       = down[(size_t)op * 128 + tid];
        sx[128 + tid] = up[(size_t)op * 128 + tid];
    }
    __syncthreads();

    {   // attention_state
        float acc = 0.f;
        for (int b = 0; b < NSB; b++) acc += g_sacc[b * 257 + tid];
        g_attn[tid] = acc / swsum;
    }

    // gates: r (tid<128, sched_W) / z (tid>=128, sched_U)
    int j = tid & 127;
    const float* Wg = (tid < 128) ? schedW : schedU;
    float s = (tid < 128) ? schedWb[j] : schedUb[j];
    #pragma unroll 8
    for (int k = 0; k < 384; k += 4) {
        float4 wv = *(const float4*)(Wg + (size_t)j * 384 + k);
        float4 xv = *(const float4*)&sx[k];
        s = fmaf(wv.x, xv.x, s); s = fmaf(wv.y, xv.y, s);
        s = fmaf(wv.z, xv.z, s); s = fmaf(wv.w, xv.w, s);
    }
    float g = 1.f / (1.f + __expf(-s));
    if (tid < 128) g_rg[j] = g; else g_zg[j] = g;
}

// ---------------------------------------------------------------------------
// K3: per-chain trans + region contribution
// ---------------------------------------------------------------------------
__global__ void ag579_k3_trans(const float* __restrict__ down, const float* __restrict__ up,
                               const float* __restrict__ schedT, const float* __restrict__ schedTb,
                               const int* __restrict__ op_idx_p)
{
    __shared__ float sx[384];
    int p = blockIdx.x, tid = threadIdx.x;   // 128
    int op = op_idx_p[0];
    sx[tid]       = down[(size_t)op * 128 + tid];
    sx[128 + tid] = up[(size_t)op * 128 + tid];
    sx[256 + tid] = g_rg[tid] * g_pcache[p * 128 + tid];
    __syncthreads();
    float s = schedTb[tid];
    #pragma unroll 8
    for (int k = 0; k < 384; k += 4) {
        float4 wv = *(const float4*)(schedT + (size_t)tid * 384 + k);
        float4 xv = *(const float4*)&sx[k];
        s = fmaf(wv.x, xv.x, s); s = fmaf(wv.y, xv.y, s);
        s = fmaf(wv.z, xv.z, s); s = fmaf(wv.w, xv.w, s);
    }
    float t = tanhf(s);
    float z = g_zg[tid];
    float pc = g_pcache[p * 128 + tid];
    g_regpart[p * 128 + tid] = (1.f - z) * pc + z * t;
}

// ---------------------------------------------------------------------------
// K4: region mean, out1/out2, softmax
// ---------------------------------------------------------------------------
__global__ void ag579_k4_final(const float* __restrict__ out1W, const float* __restrict__ out1b,
                               const float* __restrict__ out2W, const float* __restrict__ out2b,
                               float* __restrict__ out)
{
    __shared__ float st[384];
    __shared__ float stmp[128];
    __shared__ float sred4[4];
    int tid = threadIdx.x;   // 128
    st[tid]       = g_attn[tid];
    st[128 + tid] = g_attn[128 + tid];
    {
        float s = 0.f;
        #pragma unroll 8
        for (int p = 0; p < PCH; p++) s += g_regpart[p * 128 + tid];
        st[256 + tid] = s * (1.f / (float)PCH);
    }
    __syncthreads();
    float a = out1b[tid];
    #pragma unroll 8
    for (int k = 0; k < 384; k += 4) {
        float4 wv = *(const float4*)(out1W + (size_t)tid * 384 + k);
        float4 xv = *(const float4*)&st[k];
        a = fmaf(wv.x, xv.x, a); a = fmaf(wv.y, xv.y, a);
        a = fmaf(wv.z, xv.z, a); a = fmaf(wv.w, xv.w, a);
    }
    stmp[tid] = a;
    __syncthreads();
    float lg = out2b[tid];
    #pragma unroll 8
    for (int k = 0; k < 128; k += 4) {
        float4 wv = *(const float4*)(out2W + (size_t)tid * 128 + k);
        float4 xv = *(const float4*)&stmp[k];
        lg = fmaf(wv.x, xv.x, lg); lg = fmaf(wv.y, xv.y, lg);
        lg = fmaf(wv.z, xv.z, lg); lg = fmaf(wv.w, xv.w, lg);
    }
    // softmax over 128
    float m = lg;
    #pragma unroll
    for (int o = 16; o; o >>= 1) m = fmaxf(m, __shfl_xor_sync(0xffffffffu, m, o));
    if ((tid & 31) == 0) sred4[tid >> 5] = m;
    __syncthreads();
    m = fmaxf(fmaxf(sred4[0], sred4[1]), fmaxf(sred4[2], sred4[3]));
    float e = __expf(lg - m);
    float ssum = e;
    #pragma unroll
    for (int o = 16; o; o >>= 1) ssum += __shfl_xor_sync(0xffffffffu, ssum, o);
    __syncthreads();
    if ((tid & 31) == 0) sred4[tid >> 5] = ssum;
    __syncthreads();
    ssum = sred4[0] + sred4[1] + sred4[2] + sred4[3];
    out[tid] = e / ssum;
}

// ---------------------------------------------------------------------------
// launch
// ---------------------------------------------------------------------------
extern "C" void kernel_launch(void* const* d_in, const int* in_sizes, int n_in,
                              void* d_out, int out_size)
{
    const float* down      = (const float*)d_in[0];
    const float* up        = (const float*)d_in[1];
    const float* last_h    = (const float*)d_in[2];
    const float* att       = (const float*)d_in[3];
    const float* act_embed = (const float*)d_in[4];
    const float* action_W  = (const float*)d_in[5];
    const float* action_b  = (const float*)d_in[6];
    const float* action_TW = (const float*)d_in[7];
    const float* action_Tb = (const float*)d_in[8];
    const float* sched_W   = (const float*)d_in[9];
    const float* sched_Wb  = (const float*)d_in[10];
    const float* sched_U   = (const float*)d_in[11];
    const float* sched_Ub  = (const float*)d_in[12];
    const float* sched_T   = (const float*)d_in[13];
    const float* sched_Tb  = (const float*)d_in[14];
    const float* out1_W    = (const float*)d_in[15];
    const float* out1_b    = (const float*)d_in[16];
    const float* out2_W    = (const float*)d_in[17];
    const float* out2_b    = (const float*)d_in[18];
    const void*  actions   = d_in[19];   // int32 or int64 — detected on device
    const void*  parent    = d_in[20];
    const int*   op_idx    = (const int*)d_in[21];

    int sms = 148;
    cudaDeviceGetAttribute(&sms, cudaDevAttrMultiProcessorCount, 0);
    int NSB = sms - 64;          // one block per SM, single wave
    if (NSB < 8) NSB = 8;
    if (NSB > 128) NSB = 128;

    size_t smem = sizeof(MainSmem);
    cudaFuncSetAttribute(ag579_main_kernel, cudaFuncAttributeMaxDynamicSharedMemorySize, (int)smem);

    ag579_k0_setup<<<65, 256>>>(att, last_h, action_W, action_TW);
    ag579_main_kernel<<<64 + NSB, 512, smem>>>(down, up, act_embed, action_b, action_Tb,
                                               actions, parent, NSB);
    ag579_k2_combine<<<1, 256>>>(down, up, sched_W, sched_Wb, sched_U, sched_Ub, op_idx, NSB);
    ag579_k3_trans<<<64, 128>>>(down, up, sched_T, sched_Tb, op_idx);
    ag579_k4_final<<<1, 128>>>(out1_W, out1_b, out2_W, out2_b, (float*)d_out);
}

// round 17
// speedup vs baseline: 1.0563x; 1.0563x over previous
#include <cuda_runtime.h>
#include <cuda_fp16.h>
#include <cstdint>
#include <cstddef>
#include <math_constants.h>

// Problem constants (fixed by the dataset)
#define NROWS 500000
#define HDIM  128
#define PCH   64
#define LSTEPS 50

// ---------------------------------------------------------------------------
// Device scratch (static __device__ arrays only — no allocation allowed)
// ---------------------------------------------------------------------------
__device__ __align__(16) uint2 g_W2[64 * 256];   // action_W  fp16, packed [kgroup][j]
__device__ __align__(16) uint2 g_TW2[64 * 128];  // action_TW fp16, packed [kgroup][j]
__device__ __align__(16) float g_v[256];         // attention @ last_h
__device__ __align__(16) float g_pcache[PCH * HDIM];
__device__ __align__(16) float g_sacc[128 * 257];   // per-stream-block: 256 acc + wsum
__device__ __align__(16) float g_attn[256];
__device__ __align__(16) float g_rg[HDIM];
__device__ __align__(16) float g_zg[HDIM];
__device__ __align__(16) float g_x[256];        // [down[op], up[op]]
__device__ __align__(16) float g_hm[128];       // mean of p_cache
__device__ __align__(16) float g_region[128];   // mean over p of regpart
__device__ __align__(16) float g_tmp[128];      // out1 result

// RNN shared-memory layout (dynamic smem): ~198 KB, forces 1 block/SM
struct __align__(16) MainSmem {
    uint2 W2[64 * 256];     // 128 KB
    uint2 TW2[64 * 128];    //  64 KB
    float bA[256];
    float bT[128];
    float xh[256];          // [x (128) | h (128)]
    float rh[128];          // r * h
    float zb[128];          // z gate
    float hcur[128];
    float red[512];         // split-k partials
    int   acts[64];         // staged action ids for this chain
};

// Dtype-agnostic integer-index read: is64 selects int64 vs int32 layout.
__device__ __forceinline__ int ag579_read_idx(const void* buf, int i, int is64) {
    if (is64) return (int)((const long long*)buf)[i];
    return ((const int*)buf)[i];
}

__device__ __forceinline__ float ag579_dot4(float4 a, float4 b) {
    return fmaf(a.x, b.x, fmaf(a.y, b.y, fmaf(a.z, b.z, a.w * b.w)));
}

// ---------------------------------------------------------------------------
// K0: v = attention @ last_h  (block 0), weight transpose+fp16 (blocks 1..64)
// ---------------------------------------------------------------------------
__global__ void ag579_k0_setup(const float* __restrict__ att, const float* __restrict__ lh,
                               const float* __restrict__ W, const float* __restrict__ TW)
{
    int b = blockIdx.x, tid = threadIdx.x;
    if (b == 0) {
        __shared__ float s_lh[128];
        if (tid < 128) s_lh[tid] = lh[tid];
        __syncthreads();
        int w = tid >> 5, l = tid & 31;
        float4 lv = *(const float4*)&s_lh[l * 4];
        #pragma unroll 4
        for (int t = 0; t < 32; t++) {
            int i = w + 8 * t;   // 256 rows over 8 warps
            float4 a = *(const float4*)(att + (size_t)i * 128 + l * 4);
            float p = a.x * lv.x + a.y * lv.y + a.z * lv.z + a.w * lv.w;
            #pragma unroll
            for (int o = 16; o; o >>= 1) p += __shfl_xor_sync(0xffffffffu, p, o);
            if (l == 0) g_v[i] = p;
        }
    } else {
        int kg = b - 1;   // 0..63  -> k = 4*kg .. 4*kg+3
        {
            float4 wv = *(const float4*)(W + (size_t)tid * 256 + kg * 4);
            __half2 ha = __floats2half2_rn(wv.x, wv.y);
            __half2 hb = __floats2half2_rn(wv.z, wv.w);
            uint2 o;
            o.x = *reinterpret_cast<unsigned int*>(&ha);
            o.y = *reinterpret_cast<unsigned int*>(&hb);
            g_W2[kg * 256 + tid] = o;
        }
        if (tid < 128) {
            float4 wv = *(const float4*)(TW + (size_t)tid * 256 + kg * 4);
            __half2 ha = __floats2half2_rn(wv.x, wv.y);
            __half2 hb = __floats2half2_rn(wv.z, wv.w);
            uint2 o;
            o.x = *reinterpret_cast<unsigned int*>(&ha);
            o.y = *reinterpret_cast<unsigned int*>(&hb);
            g_TW2[kg * 128 + tid] = o;
        }
    }
}

// ---------------------------------------------------------------------------
// Main kernel: blocks [0,64) = RNN chains; blocks [64, 64+NSB) = streaming
// ---------------------------------------------------------------------------
__global__ void __launch_bounds__(512, 1)
ag579_main_kernel(const float* __restrict__ down, const float* __restrict__ up,
                  const float* __restrict__ act_embed,
                  const float* __restrict__ action_b, const float* __restrict__ action_Tb,
                  const void* __restrict__ actions_raw, const void* __restrict__ parent_raw,
                  int NSB)
{
    extern __shared__ __align__(16) char smem_raw[];
    int tid = threadIdx.x;

    if (blockIdx.x < 64) {
        // ===================== RNN chain block =====================
        MainSmem* sm = (MainSmem*)smem_raw;
        __shared__ int s_is64;
        int p = blockIdx.x;

        if (tid == 0) {
            const int* a32 = (const int*)actions_raw;
            int z = 1;
            #pragma unroll
            for (int i = 0; i < 16; i++) z &= (a32[2 * i + 1] == 0);
            s_is64 = z;
        }
        {
            const uint4* src = (const uint4*)g_W2;
            uint4* dst = (uint4*)sm->W2;
            for (int i = tid; i < 8192; i += 512) dst[i] = src[i];
            const uint4* src2 = (const uint4*)g_TW2;
            uint4* dst2 = (uint4*)sm->TW2;
            for (int i = tid; i < 4096; i += 512) dst2[i] = src2[i];
        }
        __syncthreads();

        int is64 = s_is64;
        if (tid < 256) sm->bA[tid] = action_b[tid];
        else if (tid < 384) sm->bT[tid - 256] = action_Tb[tid - 256];
        else if (tid >= 448 && tid < 448 + LSTEPS)
            sm->acts[tid - 448] = ag579_read_idx(actions_raw, p * LSTEPS + (tid - 448), is64);
        if (tid < 128) {
            int par = ag579_read_idx(parent_raw, p, is64);
            float h0 = down[(size_t)par * 128 + tid];
            sm->hcur[tid] = h0;
            sm->xh[128 + tid] = h0;
            int a0 = ag579_read_idx(actions_raw, p * LSTEPS, is64);
            sm->xh[tid] = act_embed[(size_t)a0 * 128 + tid];
        }
        __syncthreads();

        int j    = tid & 255, half = tid >> 8;
        int jb   = tid & 127, q    = tid >> 7;
        const float* xsrcB = (q < 2) ? sm->xh : sm->rh;
        int goffB = (q < 2) ? 0 : 128;

        for (int l = 0; l < LSTEPS; l++) {
            float xnext = 0.f;
            if (tid < 128 && l < LSTEPS - 1) {
                int an = sm->acts[l + 1];
                xnext = __ldg(&act_embed[(size_t)an * 128 + tid]);
            }

            float sum = 0.f;
            #pragma unroll
            for (int i = 0; i < 32; i++) {
                int kg = half * 32 + i;
                uint2 w = sm->W2[kg * 256 + j];
                float4 xv = *(const float4*)&sm->xh[kg * 4];
                __half2 h01 = *reinterpret_cast<__half2*>(&w.x);
                __half2 h23 = *reinterpret_cast<__half2*>(&w.y);
                float2 f01 = __half22float2(h01);
                float2 f23 = __half22float2(h23);
                sum = fmaf(f01.x, xv.x, sum);
                sum = fmaf(f01.y, xv.y, sum);
                sum = fmaf(f23.x, xv.z, sum);
                sum = fmaf(f23.y, xv.w, sum);
            }
            sm->red[tid] = sum;
            __syncthreads();
            if (tid < 256) {
                float s = sm->red[tid] + sm->red[tid + 256] + sm->bA[tid];
                float a = 1.f / (1.f + __expf(-s));
                if (tid < 128) sm->rh[tid] = a * sm->hcur[tid];
                else           sm->zb[tid - 128] = a;
            }
            __syncthreads();

            sum = 0.f;
            #pragma unroll
            for (int i = 0; i < 16; i++) {
                int kg = q * 16 + i;
                uint2 w = sm->TW2[kg * 128 + jb];
                float4 xv = *(const float4*)&xsrcB[kg * 4 - goffB];
                __half2 h01 = *reinterpret_cast<__half2*>(&w.x);
                __half2 h23 = *reinterpret_cast<__half2*>(&w.y);
                float2 f01 = __half22float2(h01);
                float2 f23 = __half22float2(h23);
                sum = fmaf(f01.x, xv.x, sum);
                sum = fmaf(f01.y, xv.y, sum);
                sum = fmaf(f23.x, xv.z, sum);
                sum = fmaf(f23.y, xv.w, sum);
            }
            sm->red[tid] = sum;
            __syncthreads();
            if (tid < 128) {
                float s = sm->red[tid] + sm->red[tid + 128] +
                          sm->red[tid + 256] + sm->red[tid + 384] + sm->bT[tid];
                float t = tanhf(s);
                float z = sm->zb[tid];
                float h = sm->hcur[tid];
                float hn = (1.f - z) * h + z * t;
                sm->hcur[tid] = hn;
                sm->xh[128 + tid] = hn;
                if (l < LSTEPS - 1) sm->xh[tid] = xnext;
            }
            __syncthreads();
        }
        if (tid < 128) g_pcache[p * 128 + tid] = sm->hcur[tid];

    } else {
        // ===================== streaming block =====================
        int sb = blockIdx.x - 64;
        float* sred = (float*)smem_raw;    // [16][257]
        int w = tid >> 5, l = tid & 31;

        float4 vd = *(const float4*)&g_v[l * 4];
        float4 vu = *(const float4*)&g_v[128 + l * 4];

        int chunk = (NROWS + NSB - 1) / NSB;
        int r0 = sb * chunk;
        int r1 = min(NROWS, r0 + chunk);

        float4 ad = make_float4(0.f, 0.f, 0.f, 0.f);
        float4 au = make_float4(0.f, 0.f, 0.f, 0.f);
        float wsum = 0.f;

        int r = r0 + w;
        for (; r + 80 < r1; r += 96) {
            float4 d[6], u[6];
            #pragma unroll
            for (int t = 0; t < 6; t++) {
                const float* rowd = down + (size_t)(r + 16 * t) * 128;
                const float* rowu = up   + (size_t)(r + 16 * t) * 128;
                d[t] = __ldcs((const float4*)(rowd + l * 4));
                u[t] = __ldcs((const float4*)(rowu + l * 4));
            }
            #pragma unroll
            for (int t = 0; t < 6; t++) {
                float pr = d[t].x * vd.x + d[t].y * vd.y + d[t].z * vd.z + d[t].w * vd.w
                         + u[t].x * vu.x + u[t].y * vu.y + u[t].z * vu.z + u[t].w * vu.w;
                #pragma unroll
                for (int o = 16; o; o >>= 1) pr += __shfl_xor_sync(0xffffffffu, pr, o);
                wsum += pr;
                ad.x = fmaf(pr, d[t].x, ad.x); ad.y = fmaf(pr, d[t].y, ad.y);
                ad.z = fmaf(pr, d[t].z, ad.z); ad.w = fmaf(pr, d[t].w, ad.w);
                au.x = fmaf(pr, u[t].x, au.x); au.y = fmaf(pr, u[t].y, au.y);
                au.z = fmaf(pr, u[t].z, au.z); au.w = fmaf(pr, u[t].w, au.w);
            }
        }
        for (; r < r1; r += 16) {
            const float* rowd = down + (size_t)r * 128;
            const float* rowu = up   + (size_t)r * 128;
            float4 d = __ldcs((const float4*)(rowd + l * 4));
            float4 u = __ldcs((const float4*)(rowu + l * 4));
            float pr = d.x * vd.x + d.y * vd.y + d.z * vd.z + d.w * vd.w
                     + u.x * vu.x + u.y * vu.y + u.z * vu.z + u.w * vu.w;
            #pragma unroll
            for (int o = 16; o; o >>= 1) pr += __shfl_xor_sync(0xffffffffu, pr, o);
            wsum += pr;
            ad.x = fmaf(pr, d.x, ad.x); ad.y = fmaf(pr, d.y, ad.y);
            ad.z = fmaf(pr, d.z, ad.z); ad.w = fmaf(pr, d.w, ad.w);
            au.x = fmaf(pr, u.x, au.x); au.y = fmaf(pr, u.y, au.y);
            au.z = fmaf(pr, u.z, au.z); au.w = fmaf(pr, u.w, au.w);
        }

        sred[w * 257 + l * 4 + 0] = ad.x;
        sred[w * 257 + l * 4 + 1] = ad.y;
        sred[w * 257 + l * 4 + 2] = ad.z;
        sred[w * 257 + l * 4 + 3] = ad.w;
        sred[w * 257 + 128 + l * 4 + 0] = au.x;
        sred[w * 257 + 128 + l * 4 + 1] = au.y;
        sred[w * 257 + 128 + l * 4 + 2] = au.z;
        sred[w * 257 + 128 + l * 4 + 3] = au.w;
        if (l == 0) sred[w * 257 + 256] = wsum;
        __syncthreads();
        if (tid < 256) {
            float s = 0.f;
            #pragma unroll
            for (int ww = 0; ww < 16; ww++) s += sred[ww * 257 + tid];
            g_sacc[sb * 257 + tid] = s;
        } else if (tid == 256) {
            float s = 0.f;
            #pragma unroll
            for (int ww = 0; ww < 16; ww++) s += sred[ww * 257 + 256];
            g_sacc[sb * 257 + 256] = s;
        }
    }
}

// ---------------------------------------------------------------------------
// K2a: combine stream partials -> g_attn; hm; x   (1 block, 256 thr)
// ---------------------------------------------------------------------------
__global__ void ag579_k2a(const float* __restrict__ down, const float* __restrict__ up,
                          const int* __restrict__ op_idx_p, int NSB)
{
    __shared__ float swsum;
    int tid = threadIdx.x;
    int op = op_idx_p[0];
    if (tid == 0) {
        float s = 0.f;
        for (int b = 0; b < NSB; b++) s += g_sacc[b * 257 + 256];
        swsum = s;
    }
    __syncthreads();
    {
        float acc = 0.f;
        for (int b = 0; b < NSB; b++) acc += g_sacc[b * 257 + tid];
        g_attn[tid] = acc / swsum;
    }
    if (tid < 128) {
        float s = 0.f;
        #pragma unroll 8
        for (int p = 0; p < PCH; p++) s += g_pcache[p * 128 + tid];
        g_hm[tid] = s * (1.f / (float)PCH);
        g_x[tid]       = down[(size_t)op * 128 + tid];
        g_x[128 + tid] = up[(size_t)op * 128 + tid];
    }
}

// ---------------------------------------------------------------------------
// K2b: gates r/z — warp-per-output.  grid 32 (0-15: r/sched_W, 16-31: z/sched_U)
// ---------------------------------------------------------------------------
__global__ void ag579_k2b(const float* __restrict__ schedW, const float* __restrict__ schedWb,
                          const float* __restrict__ schedU, const float* __restrict__ schedUb)
{
    int warp = threadIdx.x >> 5, lane = threadIdx.x & 31;
    int b = blockIdx.x;
    int isz = (b >= 16);
    int j = (b & 15) * 8 + warp;            // 0..127
    const float* Wr = (isz ? schedU : schedW) + (size_t)j * 384;
    float4 r0 = *(const float4*)(Wr + lane * 4);
    float4 r1 = *(const float4*)(Wr + 128 + lane * 4);
    float4 r2 = *(const float4*)(Wr + 256 + lane * 4);
    float4 x0 = *(const float4*)&g_x[lane * 4];
    float4 x1 = *(const float4*)&g_x[128 + lane * 4];
    float4 x2 = *(const float4*)&g_hm[lane * 4];
    float s = ag579_dot4(r0, x0) + ag579_dot4(r1, x1) + ag579_dot4(r2, x2);
    #pragma unroll
    for (int o = 16; o; o >>= 1) s += __shfl_xor_sync(0xffffffffu, s, o);
    if (lane == 0) {
        s += (isz ? schedUb : schedWb)[j];
        float g = 1.f / (1.f + __expf(-s));
        if (isz) g_zg[j] = g; else g_rg[j] = g;
    }
}

// ---------------------------------------------------------------------------
// K3: trans + region mean — warp-per-output-row, loop over chains p.
// grid 16 × 256 thr; rp = r*p_cache cached in 32 KB smem.
// ---------------------------------------------------------------------------
__global__ void ag579_k3(const float* __restrict__ schedT, const float* __restrict__ schedTb)
{
    __shared__ float rp_s[PCH * 128];   // 32 KB: rp[p][m] = r[m]*pcache[p][m]
    __shared__ float xs[256];
    int tid = threadIdx.x;
    int warp = tid >> 5, lane = tid & 31;

    for (int i = tid; i < PCH * 128; i += 256) {
        int m = i & 127;
        rp_s[i] = g_rg[m] * g_pcache[i];
    }
    xs[tid] = g_x[tid];
    __syncthreads();

    int j = blockIdx.x * 8 + warp;          // 0..127
    const float* Tr = schedT + (size_t)j * 384;
    float4 r0 = *(const float4*)(Tr + lane * 4);
    float4 r1 = *(const float4*)(Tr + 128 + lane * 4);
    float4 r2 = *(const float4*)(Tr + 256 + lane * 4);
    float4 x0 = *(const float4*)&xs[lane * 4];
    float4 x1 = *(const float4*)&xs[128 + lane * 4];
    float Tb = schedTb[j];
    float z  = g_zg[j];
    float racc = 0.f;

    for (int p = 0; p < PCH; p++) {
        float4 rp = *(const float4*)&rp_s[p * 128 + lane * 4];
        float s = ag579_dot4(r0, x0) + ag579_dot4(r1, x1) + ag579_dot4(r2, rp);
        #pragma unroll
        for (int o = 16; o; o >>= 1) s += __shfl_xor_sync(0xffffffffu, s, o);
        if (lane == 0) {
            float t = tanhf(s + Tb);
            float pc = g_pcache[p * 128 + j];
            racc += (1.f - z) * pc + z * t;
        }
    }
    if (lane == 0) g_region[j] = racc * (1.f / (float)PCH);
}

// ---------------------------------------------------------------------------
// K4a: tmp = st @ out1_W.T + out1_b — warp-per-output.  grid 16 × 256 thr
// ---------------------------------------------------------------------------
__global__ void ag579_k4a(const float* __restrict__ out1W, const float* __restrict__ out1b)
{
    int warp = threadIdx.x >> 5, lane = threadIdx.x & 31;
    int j = blockIdx.x * 8 + warp;          // 0..127
    const float* Wr = out1W + (size_t)j * 384;
    float4 r0 = *(const float4*)(Wr + lane * 4);
    float4 r1 = *(const float4*)(Wr + 128 + lane * 4);
    float4 r2 = *(const float4*)(Wr + 256 + lane * 4);
    float4 x0 = *(const float4*)&g_attn[lane * 4];
    float4 x1 = *(const float4*)&g_attn[128 + lane * 4];
    float4 x2 = *(const float4*)&g_region[lane * 4];
    float s = ag579_dot4(r0, x0) + ag579_dot4(r1, x1) + ag579_dot4(r2, x2);
    #pragma unroll
    for (int o = 16; o; o >>= 1) s += __shfl_xor_sync(0xffffffffu, s, o);
    if (lane == 0) g_tmp[j] = s + out1b[j];
}

// ---------------------------------------------------------------------------
// K4bc: logits = tmp @ out2_W.T + out2_b, softmax.  1 block × 256 thr
// ---------------------------------------------------------------------------
__global__ void ag579_k4bc(const float* __restrict__ out2W, const float* __restrict__ out2b,
                           float* __restrict__ out)
{
    __shared__ float lg_s[128];
    __shared__ float red8[8];
    int tid = threadIdx.x;
    int warp = tid >> 5, lane = tid & 31;

    float4 t4 = *(const float4*)&g_tmp[lane * 4];
    #pragma unroll
    for (int jt = 0; jt < 16; jt++) {
        int j = warp * 16 + jt;             // 0..127
        float4 w4 = *(const float4*)(out2W + (size_t)j * 128 + lane * 4);
        float s = ag579_dot4(w4, t4);
        #pragma unroll
        for (int o = 16; o; o >>= 1) s += __shfl_xor_sync(0xffffffffu, s, o);
        if (lane == 0) lg_s[j] = s + out2b[j];
    }
    __syncthreads();

    float lg = (tid < 128) ? lg_s[tid] : -CUDART_INF_F;
    float m = lg;
    #pragma unroll
    for (int o = 16; o; o >>= 1) m = fmaxf(m, __shfl_xor_sync(0xffffffffu, m, o));
    if (lane == 0) red8[warp] = m;
    __syncthreads();
    m = red8[0];
    #pragma unroll
    for (int w2 = 1; w2 < 8; w2++) m = fmaxf(m, red8[w2]);
    float e = (tid < 128) ? __expf(lg - m) : 0.f;
    float ssum = e;
    #pragma unroll
    for (int o = 16; o; o >>= 1) ssum += __shfl_xor_sync(0xffffffffu, ssum, o);
    __syncthreads();
    if (lane == 0) red8[warp] = ssum;
    __syncthreads();
    ssum = 0.f;
    #pragma unroll
    for (int w2 = 0; w2 < 8; w2++) ssum += red8[w2];
    if (tid < 128) out[tid] = e / ssum;
}

// ---------------------------------------------------------------------------
// launch
// ---------------------------------------------------------------------------
extern "C" void kernel_launch(void* const* d_in, const int* in_sizes, int n_in,
                              void* d_out, int out_size)
{
    const float* down      = (const float*)d_in[0];
    const float* up        = (const float*)d_in[1];
    const float* last_h    = (const float*)d_in[2];
    const float* att       = (const float*)d_in[3];
    const float* act_embed = (const float*)d_in[4];
    const float* action_W  = (const float*)d_in[5];
    const float* action_b  = (const float*)d_in[6];
    const float* action_TW = (const float*)d_in[7];
    const float* action_Tb = (const float*)d_in[8];
    const float* sched_W   = (const float*)d_in[9];
    const float* sched_Wb  = (const float*)d_in[10];
    const float* sched_U   = (const float*)d_in[11];
    const float* sched_Ub  = (const float*)d_in[12];
    const float* sched_T   = (const float*)d_in[13];
    const float* sched_Tb  = (const float*)d_in[14];
    const float* out1_W    = (const float*)d_in[15];
    const float* out1_b    = (const float*)d_in[16];
    const float* out2_W    = (const float*)d_in[17];
    const float* out2_b    = (const float*)d_in[18];
    const void*  actions   = d_in[19];   // int32 or int64 — detected on device
    const void*  parent    = d_in[20];
    const int*   op_idx    = (const int*)d_in[21];

    int sms = 148;
    cudaDeviceGetAttribute(&sms, cudaDevAttrMultiProcessorCount, 0);
    int NSB = sms - 64;          // one block per SM, single wave
    if (NSB < 8) NSB = 8;
    if (NSB > 128) NSB = 128;

    size_t smem = sizeof(MainSmem);
    cudaFuncSetAttribute(ag579_main_kernel, cudaFuncAttributeMaxDynamicSharedMemorySize, (int)smem);

    ag579_k0_setup<<<65, 256>>>(att, last_h, action_W, action_TW);
    ag579_main_kernel<<<64 + NSB, 512, smem>>>(down, up, act_embed, action_b, action_Tb,
                                               actions, parent, NSB);
    ag579_k2a<<<1, 256>>>(down, up, op_idx, NSB);
    ag579_k2b<<<32, 256>>>(sched_W, sched_Wb, sched_U, sched_Ub);
    ag579_k3<<<16, 256>>>(sched_T, sched_Tb);
    ag579_k4a<<<16, 256>>>(out1_W, out1_b);
    ag579_k4bc<<<1, 256>>>(out2_W, out2_b, (float*)d_out);
}